// round 2
// baseline (speedup 1.0000x reference)
#include <cuda_runtime.h>

// Problem shape (fixed by the reference):
//   z: (16, 3, 256, 256) f32 ; out: (16, 3, 256, 256) f32
#define HID   64
#define ZCH   3
#define TD    512
#define NB    16
#define HWP   (256 * 256)          // pixels per (b, ch) plane
#define HW4   (HWP / 4)            // float4 groups per plane = 16384

// ---------------------------------------------------------------------------
// Constants, packed as float4 for vectorized loads in the main kernel.
//   g_cv[0] = (M00, M11, M22, 2*M01)
//   g_cv[1] = (2*M02, 2*M12, gamma, alpha)
//   g_cv[2] = (c, w0n, w1n, w2n)
//   g_cv[3] = (P00, P01, P02, r0)
//   g_cv[4] = (P10, P11, P12, r1)
//   g_cv[5] = (P20, P21, P22, r2)
//   g_cv[6] = (ob0, ob1, ob2, 0)
//   g_pb[b][0] = (d0, d1, d2, e)     d = 2 A^T u,  e = |u|^2,  u = zb - t(b)
//   g_pb[b][1] = (q0, q1, q2, s)     q = A^T t,    s = t . zb
// ---------------------------------------------------------------------------
__device__ float4 g_cv[7];
__device__ float4 g_pb[NB][2];

__device__ __forceinline__ float wsum(float v) {
    #pragma unroll
    for (int o = 16; o; o >>= 1) v += __shfl_xor_sync(0xffffffffu, v, o);
    return v;
}

// ---------------------------------------------------------------------------
// Prep: one block per batch, 256 threads (8 warps).
// Phase 1: stage tiny tensors in shared. Phase 2: GEMV t(b) = TW tv + tpb
// (4 lanes per output, shfl-reduced). Phase 3: every reduction is a full
// warp-parallel shfl reduction — one warp per constant family, no divergent
// serial loops.
// ---------------------------------------------------------------------------
__global__ void __launch_bounds__(256) prep_kernel(
    const float* __restrict__ tv,   // (NB, TD)
    const float* __restrict__ A,    // (HID, 3) z_proj_w
    const float* __restrict__ zpb,  // (HID,)   z_proj_b
    const float* __restrict__ tw,   // (HID, TD)
    const float* __restrict__ tpb,  // (HID,)
    const float* __restrict__ W,    // (3, HID) out_w
    const float* __restrict__ ob,   // (3,)
    const float* __restrict__ lg,   // log_gamma
    const float* __restrict__ al,   // alpha
    const float* __restrict__ cp,   // c
    const float* __restrict__ wv)   // (3,)
{
    __shared__ float t_sh[HID], u_sh[HID], zpb_sh[HID];
    __shared__ float A_sh[HID * 3], W_sh[3 * HID];

    const int b    = blockIdx.x;
    const int tid  = threadIdx.x;
    const int wid  = tid >> 5;
    const int lane = tid & 31;

    // Phase 1: stage small tensors
    if (tid < HID * 3) A_sh[tid] = A[tid];
    if (tid < 3 * HID) W_sh[tid] = W[tid];
    if (tid < HID)     zpb_sh[tid] = zpb[tid];

    // Phase 2: GEMV (does not touch staged shared; overlap is fine)
    const int o    = tid >> 2;
    const int part = tid & 3;
    {
        const float* twr = tw + o * TD + part * 128;
        const float* tvr = tv + b * TD + part * 128;
        float s = 0.f;
        #pragma unroll 8
        for (int j = 0; j < 128; j++) s = fmaf(twr[j], tvr[j], s);
        s += __shfl_xor_sync(0xffffffffu, s, 1);
        s += __shfl_xor_sync(0xffffffffu, s, 2);
        __syncthreads();                 // staged shared now visible
        if (part == 0) {
            float tval = s + tpb[o];
            t_sh[o] = tval;
            u_sh[o] = zpb_sh[o] - tval;  // u = zb - t
        }
    }
    __syncthreads();

    float* cf  = (float*)g_cv;
    float* pbf = (float*)g_pb;

    const float tl = t_sh[lane],  th = t_sh[lane + 32];
    const float ul = u_sh[lane],  uh = u_sh[lane + 32];
    const float zl = zpb_sh[lane], zh = zpb_sh[lane + 32];

    if (wid == 0) {
        // per-batch d = 2 A^T u, q = A^T t
        #pragma unroll
        for (int i = 0; i < 3; i++) {
            const float a1 = A_sh[lane * 3 + i], a2 = A_sh[(lane + 32) * 3 + i];
            float d = wsum(a1 * ul + a2 * uh);
            float q = wsum(a1 * tl + a2 * th);
            if (lane == 0) { pbf[b * 8 + i] = 2.f * d; pbf[b * 8 + 4 + i] = q; }
        }
    } else if (wid == 1) {
        // per-batch e = |u|^2, s = t . zb
        float e  = wsum(ul * ul + uh * uh);
        float s2 = wsum(tl * zl + th * zh);
        if (lane == 0) { pbf[b * 8 + 3] = e; pbf[b * 8 + 7] = s2; }
    }

    if (b == 0) {
        if (wid == 2) {
            // M = A^T A (6 unique entries; off-diagonals pre-doubled)
            const int ii[6] = {0, 1, 2, 0, 0, 1};
            const int jj[6] = {0, 1, 2, 1, 2, 2};
            #pragma unroll
            for (int k = 0; k < 6; k++) {
                float m = wsum(A_sh[lane * 3 + ii[k]] * A_sh[lane * 3 + jj[k]]
                             + A_sh[(lane + 32) * 3 + ii[k]] * A_sh[(lane + 32) * 3 + jj[k]]);
                if (lane == 0) cf[k] = (k < 3) ? m : 2.f * m;
            }
        } else if (wid == 3) {
            // P = W A  -> cf[12 + 4*i + j]
            #pragma unroll
            for (int i = 0; i < 3; i++)
                #pragma unroll
                for (int j = 0; j < 3; j++) {
                    float p = wsum(W_sh[i * HID + lane] * A_sh[lane * 3 + j]
                                 + W_sh[i * HID + lane + 32] * A_sh[(lane + 32) * 3 + j]);
                    if (lane == 0) cf[12 + 4 * i + j] = p;
                }
        } else if (wid == 4) {
            // r = W zb -> cf[15 + 4*i] ; scalars ; ob
            #pragma unroll
            for (int i = 0; i < 3; i++) {
                float rr = wsum(W_sh[i * HID + lane] * zl + W_sh[i * HID + lane + 32] * zh);
                if (lane == 0) cf[15 + 4 * i] = rr;
            }
            if (lane == 0) {
                cf[6] = expf(lg[0]);         // gamma
                cf[7] = al[0];               // alpha
                cf[8] = cp[0];               // c
                float inv = 1.f / (wv[0] + wv[1] + wv[2] + 1e-8f);
                cf[9]  = wv[0] * inv;
                cf[10] = wv[1] * inv;
                cf[11] = wv[2] * inv;
            }
            if (lane >= 1 && lane <= 3) cf[24 + lane - 1] = ob[lane - 1];
        }
    }
}

// ---------------------------------------------------------------------------
// Main: pure streaming. Each thread handles 2 float4 groups x 3 channels
// (6 front-batched loads, MLP=6). 512 blocks, batch uniform per block.
// ---------------------------------------------------------------------------
__global__ void __launch_bounds__(256) fused_main_kernel(
    const float* __restrict__ z, float* __restrict__ out)
{
    const unsigned blk = blockIdx.x;                       // 0..511
    const int b    = (int)(blk >> 5);                      // 32 blocks per batch
    const int base = (int)((blk & 31u) << 9) | (int)threadIdx.x;

    const float4* zb4 = (const float4*)(z   + (size_t)b * ZCH * HWP);
    float4*       ob4 = (float4*)      (out + (size_t)b * ZCH * HWP);
    const int pA = base, pB = base + 256;

    // front-batched streaming loads
    const float4 iA0 = __ldcs(zb4 + pA);
    const float4 iA1 = __ldcs(zb4 + pA + HW4);
    const float4 iA2 = __ldcs(zb4 + pA + 2 * HW4);
    const float4 iB0 = __ldcs(zb4 + pB);
    const float4 iB1 = __ldcs(zb4 + pB + HW4);
    const float4 iB2 = __ldcs(zb4 + pB + 2 * HW4);

    // vectorized constant loads (9 x LDG.128, broadcast)
    const float4 c0 = g_cv[0], c1 = g_cv[1], c2 = g_cv[2];
    const float4 c3 = g_cv[3], c4 = g_cv[4], c5 = g_cv[5], c6 = g_cv[6];
    const float4 p0 = g_pb[b][0], p1 = g_pb[b][1];

    const float M00 = c0.x, M11 = c0.y, M22 = c0.z, M01 = c0.w;
    const float M02 = c1.x, M12 = c1.y, ngam = -c1.z, alpha = c1.w;
    const float cc = c2.x, w0n = c2.y, w1n = c2.z, w2n = c2.w;
    const float d0 = p0.x, d1 = p0.y, d2 = p0.z, e = p0.w;
    const float q0 = p1.x, q1 = p1.y, q2 = p1.z, s = p1.w;

    auto pixel = [&](float x, float y, float zz, float& o0, float& o1, float& o2) {
        float dist = e;
        dist = fmaf(fmaf(M00, x, fmaf(M01, y, fmaf(M02, zz, d0))), x, dist);
        dist = fmaf(fmaf(M11, y, fmaf(M12, zz, d1)),               y, dist);
        dist = fmaf(fmaf(M22, zz, d2),                             zz, dist);

        float klin = fmaf(q0, x, fmaf(q1, y, fmaf(q2, zz, s)));
        float krbf = __expf(ngam * dist);
        float t1   = fmaf(alpha, klin, cc);
        float k    = fmaf(w0n, krbf, fmaf(w1n, klin, w2n * (t1 * t1)));
        float scale = 1.f + 1.f / (1.f + __expf(-k));

        o0 = fmaf(scale, fmaf(c3.x, x, fmaf(c3.y, y, fmaf(c3.z, zz, c3.w))), c6.x);
        o1 = fmaf(scale, fmaf(c4.x, x, fmaf(c4.y, y, fmaf(c4.z, zz, c4.w))), c6.y);
        o2 = fmaf(scale, fmaf(c5.x, x, fmaf(c5.y, y, fmaf(c5.z, zz, c5.w))), c6.z);
    };

    float a0[4], a1[4], a2[4], o0[4], o1[4], o2[4];

    // group A
    a0[0]=iA0.x; a0[1]=iA0.y; a0[2]=iA0.z; a0[3]=iA0.w;
    a1[0]=iA1.x; a1[1]=iA1.y; a1[2]=iA1.z; a1[3]=iA1.w;
    a2[0]=iA2.x; a2[1]=iA2.y; a2[2]=iA2.z; a2[3]=iA2.w;
    #pragma unroll
    for (int i = 0; i < 4; i++) pixel(a0[i], a1[i], a2[i], o0[i], o1[i], o2[i]);
    __stcs(ob4 + pA,           make_float4(o0[0], o0[1], o0[2], o0[3]));
    __stcs(ob4 + pA + HW4,     make_float4(o1[0], o1[1], o1[2], o1[3]));
    __stcs(ob4 + pA + 2 * HW4, make_float4(o2[0], o2[1], o2[2], o2[3]));

    // group B
    a0[0]=iB0.x; a0[1]=iB0.y; a0[2]=iB0.z; a0[3]=iB0.w;
    a1[0]=iB1.x; a1[1]=iB1.y; a1[2]=iB1.z; a1[3]=iB1.w;
    a2[0]=iB2.x; a2[1]=iB2.y; a2[2]=iB2.z; a2[3]=iB2.w;
    #pragma unroll
    for (int i = 0; i < 4; i++) pixel(a0[i], a1[i], a2[i], o0[i], o1[i], o2[i]);
    __stcs(ob4 + pB,           make_float4(o0[0], o0[1], o0[2], o0[3]));
    __stcs(ob4 + pB + HW4,     make_float4(o1[0], o1[1], o1[2], o1[3]));
    __stcs(ob4 + pB + 2 * HW4, make_float4(o2[0], o2[1], o2[2], o2[3]));
}

// ---------------------------------------------------------------------------
extern "C" void kernel_launch(void* const* d_in, const int* in_sizes, int n_in,
                              void* d_out, int out_size)
{
    const float* z    = (const float*)d_in[0];
    const float* tv   = (const float*)d_in[1];
    const float* zpw  = (const float*)d_in[2];
    const float* zpb  = (const float*)d_in[3];
    const float* tw   = (const float*)d_in[4];
    const float* tpb  = (const float*)d_in[5];
    const float* ow   = (const float*)d_in[6];
    const float* ob   = (const float*)d_in[7];
    const float* lg   = (const float*)d_in[8];
    const float* al   = (const float*)d_in[9];
    const float* cp   = (const float*)d_in[10];
    const float* wv   = (const float*)d_in[11];
    float* out = (float*)d_out;

    const int B = in_sizes[0] / (ZCH * HWP);      // 16

    prep_kernel<<<B, 256>>>(tv, zpw, zpb, tw, tpb, ow, ob, lg, al, cp, wv);
    fused_main_kernel<<<(B * HW4) / 512, 256>>>(z, out);
}

// round 3
// speedup vs baseline: 3.4060x; 3.4060x over previous
#include <cuda_runtime.h>

// Problem shape (fixed by the reference):
//   z: (16, 3, 256, 256) f32 ; out: (16, 3, 256, 256) f32
#define HID   64
#define ZCH   3
#define TD    512
#define NB    16
#define HWP   (256 * 256)          // pixels per (b, ch) plane
#define HW4   (HWP / 4)            // float4 groups per plane = 16384

// ---------------------------------------------------------------------------
// Constants, packed as float4 for vectorized loads in the main kernel.
//   g_cv[0] = (M00, M11, M22, 2*M01)
//   g_cv[1] = (2*M02, 2*M12, gamma, alpha)
//   g_cv[2] = (c, w0n, w1n, w2n)
//   g_cv[3] = (P00, P01, P02, r0)
//   g_cv[4] = (P10, P11, P12, r1)
//   g_cv[5] = (P20, P21, P22, r2)
//   g_cv[6] = (ob0, ob1, ob2, 0)
//   g_pb[b][0] = (d0, d1, d2, e)     d = 2 A^T u,  e = |u|^2,  u = zb - t(b)
//   g_pb[b][1] = (q0, q1, q2, s)     q = A^T t,    s = t . zb
// ---------------------------------------------------------------------------
__device__ float4 g_cv[7];
__device__ float4 g_pb[NB][2];

__device__ __forceinline__ float wsum(float v) {
    #pragma unroll
    for (int o = 16; o; o >>= 1) v += __shfl_xor_sync(0xffffffffu, v, o);
    return v;
}

// ---------------------------------------------------------------------------
// Prep: one block per batch, 256 threads (8 warps).
// GEMV is now COALESCED: warp w computes outputs o = 8w..8w+7; each lane
// reads consecutive float4s of row o (LDG.128, 1 wavefront per load) and
// dots against the shared-staged tv row. 32 LDG.128 per warp total, vs the
// previous layout's ~4096 L1tex wavefronts per warp.
// ---------------------------------------------------------------------------
__global__ void __launch_bounds__(256) prep_kernel(
    const float* __restrict__ tv,   // (NB, TD)
    const float* __restrict__ A,    // (HID, 3) z_proj_w
    const float* __restrict__ zpb,  // (HID,)   z_proj_b
    const float* __restrict__ tw,   // (HID, TD)
    const float* __restrict__ tpb,  // (HID,)
    const float* __restrict__ W,    // (3, HID) out_w
    const float* __restrict__ ob,   // (3,)
    const float* __restrict__ lg,   // log_gamma
    const float* __restrict__ al,   // alpha
    const float* __restrict__ cp,   // c
    const float* __restrict__ wv)   // (3,)
{
    __shared__ float4 tv_sh[TD / 4];                  // 128 float4
    __shared__ float t_sh[HID], u_sh[HID], zpb_sh[HID];
    __shared__ float A_sh[HID * 3], W_sh[3 * HID];

    const int b    = blockIdx.x;
    const int tid  = threadIdx.x;
    const int wid  = tid >> 5;
    const int lane = tid & 31;

    // Stage small tensors (coalesced)
    if (tid < TD / 4)   tv_sh[tid]  = ((const float4*)(tv + b * TD))[tid];
    if (tid < HID * 3)  A_sh[tid]   = A[tid];
    if (tid < 3 * HID)  W_sh[tid]   = W[tid];
    if (tid < HID)      zpb_sh[tid] = zpb[tid];
    __syncthreads();

    // Coalesced GEMV: t(b) = TW @ tv(b) + tpb
    const float4* tw4 = (const float4*)tw;
    #pragma unroll
    for (int j = 0; j < 8; j++) {
        const int o = wid * 8 + j;
        float s = 0.f;
        #pragma unroll
        for (int k = 0; k < 4; k++) {
            const float4 a = tw4[o * (TD / 4) + k * 32 + lane];
            const float4 v = tv_sh[k * 32 + lane];
            s = fmaf(a.x, v.x, fmaf(a.y, v.y, fmaf(a.z, v.z, fmaf(a.w, v.w, s))));
        }
        s = wsum(s);
        if (lane == 0) {
            const float tval = s + tpb[o];
            t_sh[o] = tval;
            u_sh[o] = zpb_sh[o] - tval;   // u = zb - t
        }
    }
    __syncthreads();

    float* cf  = (float*)g_cv;
    float* pbf = (float*)g_pb;

    const float tl = t_sh[lane],   th = t_sh[lane + 32];
    const float ul = u_sh[lane],   uh = u_sh[lane + 32];
    const float zl = zpb_sh[lane], zh = zpb_sh[lane + 32];

    if (wid == 0) {
        // per-batch d = 2 A^T u, q = A^T t
        #pragma unroll
        for (int i = 0; i < 3; i++) {
            const float a1 = A_sh[lane * 3 + i], a2 = A_sh[(lane + 32) * 3 + i];
            float d = wsum(a1 * ul + a2 * uh);
            float q = wsum(a1 * tl + a2 * th);
            if (lane == 0) { pbf[b * 8 + i] = 2.f * d; pbf[b * 8 + 4 + i] = q; }
        }
    } else if (wid == 1) {
        // per-batch e = |u|^2, s = t . zb
        float e  = wsum(ul * ul + uh * uh);
        float s2 = wsum(tl * zl + th * zh);
        if (lane == 0) { pbf[b * 8 + 3] = e; pbf[b * 8 + 7] = s2; }
    }

    if (b == 0) {
        if (wid == 2) {
            // M = A^T A (6 unique entries; off-diagonals pre-doubled)
            const int ii[6] = {0, 1, 2, 0, 0, 1};
            const int jj[6] = {0, 1, 2, 1, 2, 2};
            #pragma unroll
            for (int k = 0; k < 6; k++) {
                float m = wsum(A_sh[lane * 3 + ii[k]] * A_sh[lane * 3 + jj[k]]
                             + A_sh[(lane + 32) * 3 + ii[k]] * A_sh[(lane + 32) * 3 + jj[k]]);
                if (lane == 0) cf[k] = (k < 3) ? m : 2.f * m;
            }
        } else if (wid == 3) {
            // P = W A  -> cf[12 + 4*i + j]
            #pragma unroll
            for (int i = 0; i < 3; i++)
                #pragma unroll
                for (int j = 0; j < 3; j++) {
                    float p = wsum(W_sh[i * HID + lane] * A_sh[lane * 3 + j]
                                 + W_sh[i * HID + lane + 32] * A_sh[(lane + 32) * 3 + j]);
                    if (lane == 0) cf[12 + 4 * i + j] = p;
                }
        } else if (wid == 4) {
            // r = W zb -> cf[15 + 4*i] ; scalars ; ob
            #pragma unroll
            for (int i = 0; i < 3; i++) {
                float rr = wsum(W_sh[i * HID + lane] * zl + W_sh[i * HID + lane + 32] * zh);
                if (lane == 0) cf[15 + 4 * i] = rr;
            }
            if (lane == 0) {
                cf[6] = expf(lg[0]);         // gamma
                cf[7] = al[0];               // alpha
                cf[8] = cp[0];               // c
                float inv = 1.f / (wv[0] + wv[1] + wv[2] + 1e-8f);
                cf[9]  = wv[0] * inv;
                cf[10] = wv[1] * inv;
                cf[11] = wv[2] * inv;
            }
            if (lane >= 1 && lane <= 3) cf[24 + lane - 1] = ob[lane - 1];
        }
    }
}

// ---------------------------------------------------------------------------
// Main: pure streaming, R1's measured-best shape (1024 blocks, 1 float4
// group x 3 channels per thread, plain cached loads) + packed constants.
// ---------------------------------------------------------------------------
__global__ void __launch_bounds__(256) fused_main_kernel(
    const float* __restrict__ z, float* __restrict__ out)
{
    const unsigned g  = blockIdx.x * 256u + threadIdx.x;
    const int b  = (int)(g >> 14);        // / HW4
    const int p4 = (int)(g & (HW4 - 1));

    const float4* zb4 = (const float4*)(z   + (size_t)b * ZCH * HWP);
    float4*       ob4 = (float4*)      (out + (size_t)b * ZCH * HWP);

    // front-batched data loads (MLP=3)
    const float4 v0 = zb4[p4];
    const float4 v1 = zb4[p4 + HW4];
    const float4 v2 = zb4[p4 + 2 * HW4];

    // vectorized constant loads (9 x LDG.128, broadcast)
    const float4 c0 = g_cv[0], c1 = g_cv[1], c2 = g_cv[2];
    const float4 c3 = g_cv[3], c4 = g_cv[4], c5 = g_cv[5], c6 = g_cv[6];
    const float4 p0 = g_pb[b][0], p1 = g_pb[b][1];

    const float M00 = c0.x, M11 = c0.y, M22 = c0.z, M01 = c0.w;
    const float M02 = c1.x, M12 = c1.y, ngam = -c1.z, alpha = c1.w;
    const float cc = c2.x, w0n = c2.y, w1n = c2.z, w2n = c2.w;
    const float d0 = p0.x, d1 = p0.y, d2 = p0.z, e = p0.w;
    const float q0 = p1.x, q1 = p1.y, q2 = p1.z, s = p1.w;

    const float a0[4] = { v0.x, v0.y, v0.z, v0.w };
    const float a1[4] = { v1.x, v1.y, v1.z, v1.w };
    const float a2[4] = { v2.x, v2.y, v2.z, v2.w };
    float o0[4], o1[4], o2[4];

    #pragma unroll
    for (int i = 0; i < 4; i++) {
        const float x = a0[i], y = a1[i], zz = a2[i];

        // dist = z'Mz + d.z + e
        float dist = e;
        dist = fmaf(fmaf(M00, x, fmaf(M01, y, fmaf(M02, zz, d0))), x, dist);
        dist = fmaf(fmaf(M11, y, fmaf(M12, zz, d1)),               y, dist);
        dist = fmaf(fmaf(M22, zz, d2),                             zz, dist);

        // k_lin = q.z + s
        float klin = fmaf(q0, x, fmaf(q1, y, fmaf(q2, zz, s)));

        float krbf = __expf(ngam * dist);
        float t1   = fmaf(alpha, klin, cc);
        float k    = fmaf(w0n, krbf, fmaf(w1n, klin, w2n * (t1 * t1)));
        float scale = 1.f + 1.f / (1.f + __expf(-k));   // 1 + sigmoid(k)

        o0[i] = fmaf(scale, fmaf(c3.x, x, fmaf(c3.y, y, fmaf(c3.z, zz, c3.w))), c6.x);
        o1[i] = fmaf(scale, fmaf(c4.x, x, fmaf(c4.y, y, fmaf(c4.z, zz, c4.w))), c6.y);
        o2[i] = fmaf(scale, fmaf(c5.x, x, fmaf(c5.y, y, fmaf(c5.z, zz, c5.w))), c6.z);
    }

    ob4[p4]           = make_float4(o0[0], o0[1], o0[2], o0[3]);
    ob4[p4 + HW4]     = make_float4(o1[0], o1[1], o1[2], o1[3]);
    ob4[p4 + 2 * HW4] = make_float4(o2[0], o2[1], o2[2], o2[3]);
}

// ---------------------------------------------------------------------------
extern "C" void kernel_launch(void* const* d_in, const int* in_sizes, int n_in,
                              void* d_out, int out_size)
{
    const float* z    = (const float*)d_in[0];
    const float* tv   = (const float*)d_in[1];
    const float* zpw  = (const float*)d_in[2];
    const float* zpb  = (const float*)d_in[3];
    const float* tw   = (const float*)d_in[4];
    const float* tpb  = (const float*)d_in[5];
    const float* ow   = (const float*)d_in[6];
    const float* ob   = (const float*)d_in[7];
    const float* lg   = (const float*)d_in[8];
    const float* al   = (const float*)d_in[9];
    const float* cp   = (const float*)d_in[10];
    const float* wv   = (const float*)d_in[11];
    float* out = (float*)d_out;

    const int B = in_sizes[0] / (ZCH * HWP);      // 16

    prep_kernel<<<B, 256>>>(tv, zpw, zpb, tw, tpb, ow, ob, lg, al, cp, wv);
    fused_main_kernel<<<(B * HW4) / 256, 256>>>(z, out);
}